// round 9
// baseline (speedup 1.0000x reference)
#include <cuda_runtime.h>
#include <cstdint>

#define RADIUS 5
#define RS 11
#define EMB 128
#define BB 32
#define LL 512
#define C_BLK 16                 // outputs per block
#define T_BLK (C_BLK + 2*RADIUS) // 26 tokens per block
#define SLOTS 8
#define SLOT_B (RS * EMB * 4)    // 5632 B: max run (11 rows)
#define CW 4                     // consumer warps
#define THREADS ((CW + 1) * 32)  // 160

__device__ __forceinline__ uint32_t smem_u32(const void* p) {
    uint32_t a;
    asm("{ .reg .u64 t; cvta.to.shared.u64 t, %1; cvt.u32.u64 %0, t; }"
        : "=r"(a) : "l"(p));
    return a;
}
__device__ __forceinline__ void mbar_init(uint32_t a, uint32_t c) {
    asm volatile("mbarrier.init.shared.b64 [%0], %1;" :: "r"(a), "r"(c) : "memory");
}
__device__ __forceinline__ void mbar_expect_tx(uint32_t a, uint32_t bytes) {
    asm volatile("mbarrier.arrive.expect_tx.shared.b64 _, [%0], %1;"
                 :: "r"(a), "r"(bytes) : "memory");
}
__device__ __forceinline__ void mbar_arrive(uint32_t a) {
    asm volatile("mbarrier.arrive.shared.b64 _, [%0];" :: "r"(a) : "memory");
}
__device__ __forceinline__ void mbar_wait(uint32_t a, uint32_t parity) {
    asm volatile(
        "{\n\t.reg .pred P;\n"
        "W_%=:\n\t"
        "mbarrier.try_wait.parity.acquire.cta.shared::cta.b64 P, [%0], %1, 0x989680;\n\t"
        "@P bra D_%=;\n\t"
        "bra W_%=;\n"
        "D_%=:\n\t}"
        :: "r"(a), "r"(parity) : "memory");
}
__device__ __forceinline__ void bulk_g2s(uint32_t dst, const void* src,
                                         uint32_t bytes, uint32_t mbar) {
    asm volatile(
        "cp.async.bulk.shared::cta.global.mbarrier::complete_tx::bytes "
        "[%0], [%1], %2, [%3];"
        :: "r"(dst), "l"(src), "r"(bytes), "r"(mbar) : "memory");
}

// Producer/consumer block: token at position p = L0-5+t contributes rows
// j in [max(0,t-15), min(11,t+1)) of its contiguous 5632B U block, serving
// outputs i = t-j in [0,16). Producer warp bulk-copies each token's exact
// run (one DMA request, 0.5-5.6KB) into an 8-slot smem ring; 4 consumer
// warps (4 outputs each) read rows from smem and mul+max-accumulate.
// This bypasses the per-SM LDG outstanding-request cap that pinned every
// register-path variant at ~31 B/cyc/SM.
__global__ __launch_bounds__(THREADS, 1) void region_encoder_kernel(
    const int* __restrict__ seq32,
    const float* __restrict__ W,
    const float* __restrict__ U,
    float* __restrict__ out)
{
    __shared__ __align__(128) unsigned char ring[SLOTS * SLOT_B];
    __shared__ __align__(16) uint64_t mbar[2 * SLOTS];  // [2s]=full, [2s+1]=empty

    const int tid  = threadIdx.x;
    const int wid  = tid >> 5;
    const int lane = tid & 31;
    const int b    = blockIdx.x >> 5;           // 32 chunks per batch
    const int L0   = (blockIdx.x & 31) * C_BLK;

    const uint32_t mb = smem_u32(mbar);
    const uint32_t rg = smem_u32(ring);

    if (tid == 0) {
#pragma unroll
        for (int s = 0; s < SLOTS; s++) {
            mbar_init(mb + (2 * s) * 8, 1);       // full: producer arrives
            mbar_init(mb + (2 * s + 1) * 8, CW);  // empty: 4 consumer warps
        }
    }
    __syncthreads();

    if (wid == CW) {
        // ---------------- producer warp ----------------
        // dtype detection (lanes 26..31 sample odd words: int64 => all zero)
        int det = 0;
        if (lane >= T_BLK) det = seq32[((lane - T_BLK) << 1) + 1];

        const int p    = L0 - RADIUS + lane;
        const bool inb = (lane < T_BLK) && ((unsigned)p < (unsigned)LL);
        const int idx  = b * LL + p;
        int tok = inb ? __ldg(seq32 + idx) : 0;
        const unsigned ball = __ballot_sync(0xffffffffu, det != 0);
        if (ball == 0u) tok = inb ? __ldg(seq32 + (idx << 1)) : 0;

        int s = 0, ph = 1;  // producer phase starts flipped: first waits pass
        for (int t = 0; t < T_BLK; t++) {
            mbar_wait(mb + (2 * s + 1) * 8, (uint32_t)ph);  // wait empty
            const int tk = __shfl_sync(0xffffffffu, tok, t);
            const int lo = max(0, t - (C_BLK - 1));
            const int hi = min(RS, t + 1);
            const uint32_t sz = (uint32_t)(hi - lo) * (EMB * 4);
            if (lane == 0) {
                const uint32_t full = mb + (2 * s) * 8;
                mbar_expect_tx(full, sz);
                bulk_g2s(rg + s * SLOT_B,
                         (const char*)U + ((size_t)tk * RS + lo) * (EMB * 4),
                         sz, full);
            }
            if (++s == SLOTS) { s = 0; ph ^= 1; }
        }
    } else {
        // ---------------- consumer warp: outputs L0 + 4*wid + [0,4) ----------------
        const int base_i = 4 * wid;

        int det = 0;
        if (lane >= 4) det = seq32[((lane - 4) << 1) + 1];
        const int cpos = b * LL + L0 + base_i + lane;
        int ct = (lane < 4) ? __ldg(seq32 + cpos) : 0;
        const unsigned ball = __ballot_sync(0xffffffffu, det != 0);
        if (ball == 0u && lane < 4) ct = __ldg(seq32 + (cpos << 1));

        float4 w[4]; float msk[4]; float4 acc[4];
#pragma unroll
        for (int ii = 0; ii < 4; ii++) {
            const int c = __shfl_sync(0xffffffffu, ct, ii);
            w[ii]  = __ldg(reinterpret_cast<const float4*>(W + (size_t)c * EMB) + lane);
            msk[ii] = (c != 0) ? 1.0f : 0.0f;
            acc[ii] = make_float4(-INFINITY, -INFINITY, -INFINITY, -INFINITY);
        }

        int s = 0, ph = 0;
        for (int t = 0; t < T_BLK; t++) {
            mbar_wait(mb + (2 * s) * 8, (uint32_t)ph);  // wait full (acquire)
            const int lo = max(0, t - (C_BLK - 1));
            const float4* slot = reinterpret_cast<const float4*>(ring + s * SLOT_B);
#pragma unroll
            for (int ii = 0; ii < 4; ii++) {
                const int j = t - (base_i + ii);
                if (j >= 0 && j < RS) {
                    const float4 u = slot[(j - lo) * (EMB / 4) + lane];
                    acc[ii].x = fmaxf(acc[ii].x, u.x * w[ii].x);
                    acc[ii].y = fmaxf(acc[ii].y, u.y * w[ii].y);
                    acc[ii].z = fmaxf(acc[ii].z, u.z * w[ii].z);
                    acc[ii].w = fmaxf(acc[ii].w, u.w * w[ii].w);
                }
            }
            __syncwarp();                    // all lanes done reading the slot
            if (lane == 0) mbar_arrive(mb + (2 * s + 1) * 8);
            if (++s == SLOTS) { s = 0; ph ^= 1; }
        }

#pragma unroll
        for (int ii = 0; ii < 4; ii++) {
            float4 h;
            h.x = acc[ii].x * msk[ii];
            h.y = acc[ii].y * msk[ii];
            h.z = acc[ii].z * msk[ii];
            h.w = acc[ii].w * msk[ii];
            __stcs(reinterpret_cast<float4*>(
                       out + (size_t)(b * LL + L0 + base_i + ii) * EMB) + lane, h);
        }
    }
}

extern "C" void kernel_launch(void* const* d_in, const int* in_sizes, int n_in,
                              void* d_out, int out_size) {
    const int*   seq32 = (const int*)d_in[0];
    const float* W     = (const float*)d_in[1];
    const float* U     = (const float*)d_in[2];
    float*       out   = (float*)d_out;

    const int blocks = BB * (LL / C_BLK);  // 1024
    region_encoder_kernel<<<blocks, THREADS>>>(seq32, W, U, out);
}